// round 5
// baseline (speedup 1.0000x reference)
#include <cuda_runtime.h>
#include <math.h>

// ---------------- problem constants ----------------
#define BB   2
#define SS   336
#define VV   8
#define DD   256
#define HH   8
#define DK   32
#define PP   96
#define NT   (BB*VV*SS)      // 5376 tokens
#define SD   (SS*DD)         // 86016
#define RSQRT_DK 0.17677669529663687f   // 1/sqrt(32)

// ---------------- scratch (static device allocs are allowed) ----------------
__device__ float g_E[NT*DD];
__device__ float g_Q[NT*DD];
__device__ float g_K[NT*DD];
__device__ float g_V[NT*DD];
__device__ float g_O[NT*DD];   // attention output (pre-Wo)
__device__ float g_P[NT*DD];   // Wo projection result

// ---------------- embed: e[b,v,s,d] = x[b,s,v]*emb_w[d] + emb_b[d] ----------------
__global__ void k_embed(const float* __restrict__ x,
                        const float* __restrict__ ew,
                        const float* __restrict__ eb) {
    int idx = blockIdx.x * 256 + threadIdx.x;     // NT*DD exact
    int d = idx & 255;
    int t = idx >> 8;
    int b = t / (VV*SS);
    int r = t - b*(VV*SS);
    int v = r / SS;
    int s = r - v*SS;
    g_E[idx] = x[(b*SS + s)*VV + v] * ew[d] + eb[d];
}

// ---------------- SGEMM: C[M=5376, N=256] = A @ W + bias ----------------
// BM=128, BN=64, BK=16, 128 threads, 8x8 microtile.
#define BM 128
#define BN 64
#define BK 16

__device__ __forceinline__ void gemm_body(const float* __restrict__ A,
                                          const float* __restrict__ W,
                                          const float* __restrict__ bias,
                                          float* __restrict__ C) {
    __shared__ float As[BK][BM + 4];
    __shared__ float Bs[BK][BN];

    int tid = threadIdx.x;
    int tx = tid & 7;     // N dir: 8 threads * 8 cols
    int ty = tid >> 3;    // M dir: 16 threads * 8 rows
    int m0 = blockIdx.x * BM;
    int n0 = blockIdx.y * BN;

    float acc[8][8];
#pragma unroll
    for (int i = 0; i < 8; i++)
#pragma unroll
        for (int j = 0; j < 8; j++) acc[i][j] = 0.f;

    for (int kt = 0; kt < DD; kt += BK) {
        // A tile: 128x16 = 512 float4, 4 per thread, store transposed
#pragma unroll
        for (int i = 0; i < 4; i++) {
            int f = tid + 128*i;
            int row = f >> 2;
            int kq = f & 3;
            float4 va = *(const float4*)&A[(m0 + row)*DD + kt + kq*4];
            As[kq*4+0][row] = va.x;
            As[kq*4+1][row] = va.y;
            As[kq*4+2][row] = va.z;
            As[kq*4+3][row] = va.w;
        }
        // B tile: 16x64 = 256 float4, 2 per thread
#pragma unroll
        for (int i = 0; i < 2; i++) {
            int f = tid + 128*i;
            int kk = f >> 4;
            int nq = f & 15;
            *(float4*)&Bs[kk][nq*4] = *(const float4*)&W[(kt + kk)*DD + n0 + nq*4];
        }
        __syncthreads();
#pragma unroll
        for (int kk = 0; kk < BK; kk++) {
            float a[8], b[8];
#pragma unroll
            for (int i = 0; i < 8; i++) a[i] = As[kk][ty*8 + i];
#pragma unroll
            for (int j = 0; j < 8; j++) b[j] = Bs[kk][tx*8 + j];
#pragma unroll
            for (int i = 0; i < 8; i++)
#pragma unroll
                for (int j = 0; j < 8; j++) acc[i][j] += a[i]*b[j];
        }
        __syncthreads();
    }
#pragma unroll
    for (int i = 0; i < 8; i++) {
        int m = m0 + ty*8 + i;
#pragma unroll
        for (int j = 0; j < 8; j++) {
            int n = n0 + tx*8 + j;
            C[m*DD + n] = acc[i][j] + bias[n];
        }
    }
}

__global__ void __launch_bounds__(128) k_gemm_qkv(
        const float* __restrict__ Wq, const float* __restrict__ Wk, const float* __restrict__ Wv,
        const float* __restrict__ bq, const float* __restrict__ bk, const float* __restrict__ bv_) {
    const float* W; const float* bi; float* C;
    if (blockIdx.z == 0)      { W = Wq; bi = bq;  C = g_Q; }
    else if (blockIdx.z == 1) { W = Wk; bi = bk;  C = g_K; }
    else                      { W = Wv; bi = bv_; C = g_V; }
    gemm_body(g_E, W, bi, C);
}

__global__ void __launch_bounds__(128) k_gemm_wo(const float* __restrict__ Wo,
                                                 const float* __restrict__ bo) {
    gemm_body(g_O, Wo, bo, g_P);
}

// ---------------- time attention: groups (b,v), L=336 ----------------
// grid (3 q-chunks, 8 heads, 16 groups), 128 threads; thread = one query (112 per chunk)
__global__ void __launch_bounds__(128) k_attn_time() {
    __shared__ float Ks[112][32];
    __shared__ float Vs[112][32];

    int g  = blockIdx.z;           // (b*V+v)
    int h  = blockIdx.y;
    int qc = blockIdx.x;
    int tid = threadIdx.x;
    int qi = qc*112 + tid;         // query s, valid if tid<112
    bool active = tid < 112;

    float q[32], acc[32];
    float m = -1e30f, sum = 0.f;
    if (active) {
        const float* qp = &g_Q[(g*SS + qi)*DD + h*32];
#pragma unroll
        for (int i = 0; i < 8; i++) {
            float4 v4 = *(const float4*)&qp[i*4];
            q[i*4+0] = v4.x; q[i*4+1] = v4.y; q[i*4+2] = v4.z; q[i*4+3] = v4.w;
        }
#pragma unroll
        for (int d = 0; d < 32; d++) acc[d] = 0.f;
    }

    for (int kt = 0; kt < 3; kt++) {
        __syncthreads();
        // load 112 keys+values: 896 float4 each array, 7 per thread
#pragma unroll
        for (int i = 0; i < 7; i++) {
            int f = tid + 128*i;
            int ki = f >> 3;
            int dq = f & 7;
            int ga = (g*SS + kt*112 + ki)*DD + h*32 + dq*4;
            *(float4*)&Ks[ki][dq*4] = *(const float4*)&g_K[ga];
            *(float4*)&Vs[ki][dq*4] = *(const float4*)&g_V[ga];
        }
        __syncthreads();
        if (active) {
            for (int ki = 0; ki < 112; ki++) {
                float s = 0.f;
#pragma unroll
                for (int d = 0; d < 32; d++) s += q[d]*Ks[ki][d];
                s *= RSQRT_DK;
                float p;
                if (s <= m) {
                    p = __expf(s - m);
                } else {
                    float c = __expf(m - s);
                    sum *= c;
#pragma unroll
                    for (int d = 0; d < 32; d++) acc[d] *= c;
                    m = s;
                    p = 1.f;
                }
                sum += p;
#pragma unroll
                for (int d = 0; d < 32; d++) acc[d] += p * Vs[ki][d];
            }
        }
    }
    if (active) {
        float inv = 1.f / sum;
        float* op = &g_O[(g*SS + qi)*DD + h*32];
#pragma unroll
        for (int i = 0; i < 8; i++) {
            float4 v4;
            v4.x = acc[i*4+0]*inv; v4.y = acc[i*4+1]*inv;
            v4.z = acc[i*4+2]*inv; v4.w = acc[i*4+3]*inv;
            *(float4*)&op[i*4] = v4;
        }
    }
}

// ---------------- variable attention: groups (b,s), L=8 ----------------
// grid 672 blocks, 64 threads; thread = (h, qv)
__global__ void __launch_bounds__(64) k_attn_var() {
    __shared__ float Ks[8][256];
    __shared__ float Vs[8][256];

    int bs = blockIdx.x;
    int b = bs / SS;
    int s = bs - b*SS;
    int tid = threadIdx.x;

    // load K,V for 8 tokens x 256 d: 512 float4 each, 8 per thread
#pragma unroll
    for (int i = 0; i < 8; i++) {
        int f = tid + 64*i;
        int v = f >> 6;
        int dq = f & 63;
        int ga = ((b*VV + v)*SS + s)*DD + dq*4;
        *(float4*)&Ks[v][dq*4] = *(const float4*)&g_K[ga];
        *(float4*)&Vs[v][dq*4] = *(const float4*)&g_V[ga];
    }
    __syncthreads();

    int qv = tid & 7;
    int h  = tid >> 3;
    const float* qp = &g_Q[((b*VV + qv)*SS + s)*DD + h*32];
    float q[32];
#pragma unroll
    for (int i = 0; i < 8; i++) {
        float4 v4 = *(const float4*)&qp[i*4];
        q[i*4+0] = v4.x; q[i*4+1] = v4.y; q[i*4+2] = v4.z; q[i*4+3] = v4.w;
    }
    float sc[8];
    float mx = -1e30f;
#pragma unroll
    for (int v = 0; v < 8; v++) {
        float t = 0.f;
#pragma unroll
        for (int d = 0; d < 32; d++) t += q[d]*Ks[v][h*32 + d];
        t *= RSQRT_DK;
        sc[v] = t;
        mx = fmaxf(mx, t);
    }
    float sum = 0.f;
#pragma unroll
    for (int v = 0; v < 8; v++) { sc[v] = __expf(sc[v] - mx); sum += sc[v]; }
    float inv = 1.f / sum;

    float o[32];
#pragma unroll
    for (int d = 0; d < 32; d++) o[d] = 0.f;
#pragma unroll
    for (int v = 0; v < 8; v++)
#pragma unroll
        for (int d = 0; d < 32; d++) o[d] += sc[v]*Vs[v][h*32 + d];

    float* op = &g_O[((b*VV + qv)*SS + s)*DD + h*32];
#pragma unroll
    for (int i = 0; i < 8; i++) {
        float4 v4;
        v4.x = o[i*4+0]*inv; v4.y = o[i*4+1]*inv;
        v4.z = o[i*4+2]*inv; v4.w = o[i*4+3]*inv;
        *(float4*)&op[i*4] = v4;
    }
}

// ---------------- residual + layernorm (optionally second layernorm fused) ----------------
// 256 threads = 8 warps, warp per token, grid 672
__global__ void __launch_bounds__(256) k_ln(const float* __restrict__ g1,
                                            const float* __restrict__ b1,
                                            const float* __restrict__ g2,
                                            const float* __restrict__ b2,
                                            int do_second) {
    int lane = threadIdx.x & 31;
    int w = threadIdx.x >> 5;
    int t = blockIdx.x*8 + w;
    float x[8];
    const float* ep = &g_E[t*DD];
    const float* pp = &g_P[t*DD];
#pragma unroll
    for (int j = 0; j < 8; j++) {
        int d = lane + 32*j;
        x[j] = ep[d] + pp[d];
    }
    float sm = 0.f, sq = 0.f;
#pragma unroll
    for (int j = 0; j < 8; j++) { sm += x[j]; sq += x[j]*x[j]; }
#pragma unroll
    for (int o = 16; o; o >>= 1) {
        sm += __shfl_xor_sync(0xffffffffu, sm, o);
        sq += __shfl_xor_sync(0xffffffffu, sq, o);
    }
    float mu = sm * (1.f/256.f);
    float var = sq * (1.f/256.f) - mu*mu;
    float r = rsqrtf(var + 1e-5f);
#pragma unroll
    for (int j = 0; j < 8; j++) {
        int d = lane + 32*j;
        x[j] = (x[j] - mu)*r*g1[d] + b1[d];
    }
    if (do_second) {
        float sm2 = 0.f, sq2 = 0.f;
#pragma unroll
        for (int j = 0; j < 8; j++) { sm2 += x[j]; sq2 += x[j]*x[j]; }
#pragma unroll
        for (int o = 16; o; o >>= 1) {
            sm2 += __shfl_xor_sync(0xffffffffu, sm2, o);
            sq2 += __shfl_xor_sync(0xffffffffu, sq2, o);
        }
        float mu2 = sm2 * (1.f/256.f);
        float var2 = sq2 * (1.f/256.f) - mu2*mu2;
        float r2 = rsqrtf(var2 + 1e-5f);
#pragma unroll
        for (int j = 0; j < 8; j++) {
            int d = lane + 32*j;
            x[j] = (x[j] - mu2)*r2*g2[d] + b2[d];
        }
    }
    float* eo = &g_E[t*DD];
#pragma unroll
    for (int j = 0; j < 8; j++) eo[lane + 32*j] = x[j];
}

// ---------------- final projection ----------------
__global__ void k_out_init(const float* __restrict__ pb, float* __restrict__ out) {
    int i = blockIdx.x*256 + threadIdx.x;
    if (i < BB*PP*VV) {
        int p = (i % (PP*VV)) >> 3;
        out[i] = pb[p];
    }
}

// grid 168 k-chunks of 512; block 256 threads; thread owns 6 (bv,p) outputs
__global__ void __launch_bounds__(256) k_proj(const float* __restrict__ W,
                                              float* __restrict__ out) {
    __shared__ float Ws[64][96];
    __shared__ float Es[16][64];
    int k0 = blockIdx.x * 512;
    int tid = threadIdx.x;

    float acc[6];
    const float* erow[6];
    int wcol[6], oidx[6];
#pragma unroll
    for (int i = 0; i < 6; i++) {
        int qq = tid + 256*i;            // 0..1535
        int bv = qq / 96;
        int p  = qq - bv*96;
        acc[i] = 0.f;
        erow[i] = &Es[bv][0];
        wcol[i] = p;
        oidx[i] = (bv >> 3)*(PP*VV) + p*VV + (bv & 7);
    }

    for (int kt = 0; kt < 8; kt++) {
        int kb = k0 + kt*64;
        __syncthreads();
        // Ws: 64x96 = 1536 float4, 6 per thread
#pragma unroll
        for (int i = 0; i < 6; i++) {
            int f = tid + 256*i;
            int kk = f / 24;
            int pq = f - kk*24;
            *(float4*)&Ws[kk][pq*4] = *(const float4*)&W[(kb + kk)*PP + pq*4];
        }
        // Es: 16x64 = 256 float4, 1 per thread
        {
            int bv = tid >> 4;
            int kq = tid & 15;
            *(float4*)&Es[bv][kq*4] = *(const float4*)&g_E[bv*SD + kb + kq*4];
        }
        __syncthreads();
        for (int kk = 0; kk < 64; kk++) {
#pragma unroll
            for (int i = 0; i < 6; i++)
                acc[i] += erow[i][kk] * Ws[kk][wcol[i]];
        }
    }
#pragma unroll
    for (int i = 0; i < 6; i++)
        atomicAdd(&out[oidx[i]], acc[i]);
}

// ---------------- launch ----------------
extern "C" void kernel_launch(void* const* d_in, const int* in_sizes, int n_in,
                              void* d_out, int out_size) {
    const float* x      = (const float*)d_in[0];
    const float* emb_w  = (const float*)d_in[1];
    const float* emb_b  = (const float*)d_in[2];
    const float* Wq     = (const float*)d_in[3];
    const float* bq     = (const float*)d_in[4];
    const float* Wk     = (const float*)d_in[5];
    const float* bk     = (const float*)d_in[6];
    const float* Wv     = (const float*)d_in[7];
    const float* bv     = (const float*)d_in[8];
    const float* Wo     = (const float*)d_in[9];
    const float* bo     = (const float*)d_in[10];
    const float* ln1_g  = (const float*)d_in[11];
    const float* ln1_b  = (const float*)d_in[12];
    const float* norm_g = (const float*)d_in[13];
    const float* norm_b = (const float*)d_in[14];
    const float* proj_w = (const float*)d_in[15];
    const float* proj_b = (const float*)d_in[16];
    float* out = (float*)d_out;

    k_embed<<<NT, 256>>>(x, emb_w, emb_b);

    dim3 gq(NT/BM, DD/BN, 3);   // 42 x 4 x 3
    dim3 g1(NT/BM, DD/BN);      // 42 x 4

    for (int it = 0; it < 10; it++) {
        // phase A: attention over time axis
        k_gemm_qkv<<<gq, 128>>>(Wq, Wk, Wv, bq, bk, bv);
        k_attn_time<<<dim3(3, 8, 16), 128>>>();
        k_gemm_wo<<<g1, 128>>>(Wo, bo);
        k_ln<<<NT/8, 256>>>(ln1_g, ln1_b, norm_g, norm_b, 1);   // ln1 + inter-phase norm fused
        // phase B: attention over variable axis
        k_gemm_qkv<<<gq, 128>>>(Wq, Wk, Wv, bq, bk, bv);
        k_attn_var<<<BB*SS, 64>>>();
        k_gemm_wo<<<g1, 128>>>(Wo, bo);
        k_ln<<<NT/8, 256>>>(ln1_g, ln1_b, nullptr, nullptr, 0);
    }

    k_out_init<<<6, 256>>>(proj_b, out);
    k_proj<<<SD/512, 256>>>(proj_w, out);
}

// round 7
// speedup vs baseline: 1.7156x; 1.7156x over previous
#include <cuda_runtime.h>
#include <cuda_bf16.h>
#include <math.h>
#include <stdint.h>

// ---------------- problem constants ----------------
#define BB   2
#define SS   336
#define VV   8
#define DD   256
#define HH   8
#define DK   32
#define PP   96
#define NT   (BB*VV*SS)      // 5376 tokens
#define SD   (SS*DD)         // 86016
#define RSQRT_DK 0.17677669529663687f   // 1/sqrt(32)

// ---------------- scratch ----------------
__device__ float g_E[NT*DD];
__device__ float g_Q[NT*DD];
__device__ float g_K[NT*DD];
__device__ float g_V[NT*DD];
__device__ float g_O[NT*DD];
__device__ float g_P[NT*DD];
// transposed bf16 weight images W^T[n][k], hi/lo split: [w(4)][256][256]
__device__ __align__(16) __nv_bfloat16 g_WtH[4*65536];
__device__ __align__(16) __nv_bfloat16 g_WtL[4*65536];

// ---------------- helpers ----------------
__device__ __forceinline__ uint32_t smem_u32(const void* p) {
    uint32_t a;
    asm("{ .reg .u64 t; cvta.to.shared.u64 t, %1; cvt.u32.u64 %0, t; }" : "=r"(a) : "l"(p));
    return a;
}
__device__ __forceinline__ void ldsm4(uint32_t& r0, uint32_t& r1, uint32_t& r2, uint32_t& r3,
                                      uint32_t a) {
    asm volatile("ldmatrix.sync.aligned.m8n8.x4.shared.b16 {%0,%1,%2,%3}, [%4];"
        : "=r"(r0), "=r"(r1), "=r"(r2), "=r"(r3) : "r"(a));
}
__device__ __forceinline__ void mma16816(float* c, const uint32_t* a, const uint32_t* b) {
    asm volatile("mma.sync.aligned.m16n8k16.row.col.f32.bf16.bf16.f32 "
        "{%0,%1,%2,%3}, {%4,%5,%6,%7}, {%8,%9}, {%0,%1,%2,%3};"
        : "+f"(c[0]), "+f"(c[1]), "+f"(c[2]), "+f"(c[3])
        : "r"(a[0]), "r"(a[1]), "r"(a[2]), "r"(a[3]), "r"(b[0]), "r"(b[1]));
}
// packed f32x2 ops
typedef unsigned long long u64t;
__device__ __forceinline__ u64t pk2(float lo, float hi) {
    u64t r; asm("mov.b64 %0, {%1, %2};" : "=l"(r) : "f"(lo), "f"(hi)); return r;
}
__device__ __forceinline__ void upk2(float& lo, float& hi, u64t v) {
    asm("mov.b64 {%0, %1}, %2;" : "=f"(lo), "=f"(hi) : "l"(v));
}
__device__ __forceinline__ u64t fma2(u64t a, u64t b, u64t c) {
    u64t d; asm("fma.rn.f32x2 %0, %1, %2, %3;" : "=l"(d) : "l"(a), "l"(b), "l"(c)); return d;
}
__device__ __forceinline__ u64t mul2(u64t a, u64t b) {
    u64t d; asm("mul.rn.f32x2 %0, %1, %2;" : "=l"(d) : "l"(a), "l"(b)); return d;
}

// ---------------- embed ----------------
__global__ void k_embed(const float* __restrict__ x,
                        const float* __restrict__ ew,
                        const float* __restrict__ eb) {
    int idx = blockIdx.x * 256 + threadIdx.x;
    int d = idx & 255;
    int t = idx >> 8;
    int b = t / (VV*SS);
    int r = t - b*(VV*SS);
    int v = r / SS;
    int s = r - v*SS;
    g_E[idx] = x[(b*SS + s)*VV + v] * ew[d] + eb[d];
}

// ---------------- weight prep: W^T + bf16 hi/lo split ----------------
__global__ void k_prep(const float* __restrict__ Wq, const float* __restrict__ Wk,
                       const float* __restrict__ Wv, const float* __restrict__ Wo) {
    int e = blockIdx.x * 256 + threadIdx.x;   // 0..65535
    int w = blockIdx.y;
    int n = e >> 8, k = e & 255;
    const float* W = (w == 0) ? Wq : (w == 1) ? Wk : (w == 2) ? Wv : Wo;
    float a = W[k*256 + n];
    __nv_bfloat16 h = __float2bfloat16(a);
    __nv_bfloat16 l = __float2bfloat16(a - __bfloat162float(h));
    g_WtH[w*65536 + n*256 + k] = h;
    g_WtL[w*65536 + n*256 + k] = l;
}

// ---------------- mma.sync bf16x3 GEMM: C[5376,256] = A @ W + bias ----------------
// CTA tile 64x256, 8 warps (warp tile 32x64), K-chunks of 64, padded smem rows (144B).
#define GA_H 0
#define GA_L 9216
#define GB_H 18432
#define GB_L 55296
#define SMEM_GEMM 92160

__device__ __forceinline__ void tgemm_body(char* sm, const float* __restrict__ A,
                                           const __nv_bfloat16* __restrict__ WtH,
                                           const __nv_bfloat16* __restrict__ WtL,
                                           const float* __restrict__ bias,
                                           float* __restrict__ C) {
    const int tid = threadIdx.x;
    const int wid = tid >> 5, lane = tid & 31;
    const int m0 = blockIdx.x * 64;
    const int wm = (wid & 1) * 32;        // warp m offset within CTA (0/32)
    const int wn = (wid >> 1) * 64;       // warp n offset (0/64/128/192)
    uint32_t sb = smem_u32(sm);

    float acc[2][8][4];
#pragma unroll
    for (int i = 0; i < 2; i++)
#pragma unroll
        for (int j = 0; j < 8; j++)
#pragma unroll
            for (int q = 0; q < 4; q++) acc[i][j][q] = 0.f;

    // per-thread ldmatrix base addresses
    uint32_t aRow = wm + (lane & 7) + ((lane >> 3) & 1) * 8;
    uint32_t aBase = sb + GA_H + aRow*144 + ((lane >> 4) & 1)*16;
    uint32_t bRow = wn + (lane & 7) + ((lane >> 4) & 1) * 8;
    uint32_t bBase = sb + GB_H + bRow*144 + ((lane >> 3) & 1)*16;

    for (int kc = 0; kc < 4; kc++) {
        if (kc) __syncthreads();
        // stage A chunk: 64 rows x 64 k fp32 -> bf16 hi/lo (1024 float4)
        const float4* Ag = (const float4*)(A + m0*256 + kc*64);
#pragma unroll
        for (int i = 0; i < 4; i++) {
            int f = tid + 256*i;
            int r = f >> 4, q = f & 15;
            float4 v = Ag[r*64 + q];
            __nv_bfloat16 h0 = __float2bfloat16(v.x);
            __nv_bfloat16 h1 = __float2bfloat16(v.y);
            __nv_bfloat16 h2 = __float2bfloat16(v.z);
            __nv_bfloat16 h3 = __float2bfloat16(v.w);
            __nv_bfloat16 l0 = __float2bfloat16(v.x - __bfloat162float(h0));
            __nv_bfloat16 l1 = __float2bfloat16(v.y - __bfloat162float(h1));
            __nv_bfloat16 l2 = __float2bfloat16(v.z - __bfloat162float(h2));
            __nv_bfloat16 l3 = __float2bfloat16(v.w - __bfloat162float(h3));
            uint2 hp, lp;
            hp.x = (uint32_t)__bfloat16_as_ushort(h0) | ((uint32_t)__bfloat16_as_ushort(h1) << 16);
            hp.y = (uint32_t)__bfloat16_as_ushort(h2) | ((uint32_t)__bfloat16_as_ushort(h3) << 16);
            lp.x = (uint32_t)__bfloat16_as_ushort(l0) | ((uint32_t)__bfloat16_as_ushort(l1) << 16);
            lp.y = (uint32_t)__bfloat16_as_ushort(l2) | ((uint32_t)__bfloat16_as_ushort(l3) << 16);
            uint32_t off = (uint32_t)r*144 + (uint32_t)q*8;
            *(uint2*)(sm + GA_H + off) = hp;
            *(uint2*)(sm + GA_L + off) = lp;
        }
        // stage B chunk: 256 n-rows x 64 k bf16, hi+lo (2048 uint4 each)
        const uint4* BH = (const uint4*)(WtH + kc*64);
        const uint4* BL = (const uint4*)(WtL + kc*64);
#pragma unroll
        for (int i = 0; i < 8; i++) {
            int f = tid + 256*i;
            int r = f >> 3, q = f & 7;
            uint32_t off = (uint32_t)r*144 + (uint32_t)q*16;
            *(uint4*)(sm + GB_H + off) = BH[r*32 + q];
            *(uint4*)(sm + GB_L + off) = BL[r*32 + q];
        }
        __syncthreads();

#pragma unroll
        for (int ks = 0; ks < 4; ks++) {
            uint32_t aH[2][4], aL[2][4], bH[4][4], bL[4][4];
#pragma unroll
            for (int i = 0; i < 2; i++) {
                ldsm4(aH[i][0], aH[i][1], aH[i][2], aH[i][3],
                      aBase + (uint32_t)i*2304 + (uint32_t)ks*32);
                ldsm4(aL[i][0], aL[i][1], aL[i][2], aL[i][3],
                      aBase + (GA_L - GA_H) + (uint32_t)i*2304 + (uint32_t)ks*32);
            }
#pragma unroll
            for (int j = 0; j < 4; j++) {
                ldsm4(bH[j][0], bH[j][1], bH[j][2], bH[j][3],
                      bBase + (uint32_t)j*2304 + (uint32_t)ks*32);
                ldsm4(bL[j][0], bL[j][1], bL[j][2], bL[j][3],
                      bBase + (GB_L - GB_H) + (uint32_t)j*2304 + (uint32_t)ks*32);
            }
#pragma unroll
            for (int i = 0; i < 2; i++)
#pragma unroll
                for (int j = 0; j < 4; j++) {
                    mma16816(acc[i][2*j],   aH[i], &bH[j][0]);
                    mma16816(acc[i][2*j+1], aH[i], &bH[j][2]);
                    mma16816(acc[i][2*j],   aH[i], &bL[j][0]);
                    mma16816(acc[i][2*j+1], aH[i], &bL[j][2]);
                    mma16816(acc[i][2*j],   aL[i], &bH[j][0]);
                    mma16816(acc[i][2*j+1], aL[i], &bH[j][2]);
                }
        }
    }

    // epilogue
    int tr = lane >> 2, tc = (lane & 3) * 2;
    float2 bb[8];
#pragma unroll
    for (int j = 0; j < 8; j++) {
        int cl = wn + 8*j + tc;
        bb[j].x = __ldg(&bias[cl]);
        bb[j].y = __ldg(&bias[cl+1]);
    }
#pragma unroll
    for (int i = 0; i < 2; i++) {
        int r0 = m0 + wm + 16*i + tr;
#pragma unroll
        for (int j = 0; j < 8; j++) {
            int cl = wn + 8*j + tc;
            float2 o0, o1;
            o0.x = acc[i][j][0] + bb[j].x; o0.y = acc[i][j][1] + bb[j].y;
            o1.x = acc[i][j][2] + bb[j].x; o1.y = acc[i][j][3] + bb[j].y;
            *(float2*)&C[r0*256 + cl]     = o0;
            *(float2*)&C[(r0+8)*256 + cl] = o1;
        }
    }
}

__global__ void __launch_bounds__(256, 1)
k_tgemm_qkv(const float* __restrict__ bq, const float* __restrict__ bk,
            const float* __restrict__ bv) {
    extern __shared__ char sm[];
    int y = blockIdx.y;
    const __nv_bfloat16* WH = &g_WtH[y*65536];
    const __nv_bfloat16* WL = &g_WtL[y*65536];
    const float* bias = (y == 0) ? bq : (y == 1) ? bk : bv;
    float* C = (y == 0) ? g_Q : (y == 1) ? g_K : g_V;
    tgemm_body(sm, g_E, WH, WL, bias, C);
}

__global__ void __launch_bounds__(256, 1)
k_tgemm_wo(const float* __restrict__ bo) {
    extern __shared__ char sm[];
    tgemm_body(sm, g_O, &g_WtH[3*65536], &g_WtL[3*65536], bo, g_P);
}

// ---------------- time attention (f32x2 packed math) ----------------
__global__ void __launch_bounds__(128) k_attn_time() {
    __shared__ __align__(16) float Ks[112][32];
    __shared__ __align__(16) float Vs[112][32];

    int g  = blockIdx.z;
    int h  = blockIdx.y;
    int qc = blockIdx.x;
    int tid = threadIdx.x;
    int qi = qc*112 + tid;
    bool active = tid < 112;

    u64t q2[16], acc2[16];
    float m = -1e30f, sum = 0.f;
    if (active) {
        const float4* qp = (const float4*)&g_Q[(g*SS + qi)*DD + h*32];
#pragma unroll
        for (int i = 0; i < 8; i++) {
            float4 v4 = qp[i];
            q2[2*i]   = pk2(v4.x, v4.y);
            q2[2*i+1] = pk2(v4.z, v4.w);
        }
#pragma unroll
        for (int i = 0; i < 16; i++) acc2[i] = 0ull;
    }

    for (int kt = 0; kt < 3; kt++) {
        __syncthreads();
#pragma unroll
        for (int i = 0; i < 7; i++) {
            int f = tid + 128*i;
            int ki = f >> 3;
            int dq = f & 7;
            int ga = (g*SS + kt*112 + ki)*DD + h*32 + dq*4;
            *(float4*)&Ks[ki][dq*4] = *(const float4*)&g_K[ga];
            *(float4*)&Vs[ki][dq*4] = *(const float4*)&g_V[ga];
        }
        __syncthreads();
        if (active) {
            for (int ki = 0; ki < 112; ki++) {
                const u64t* k2 = (const u64t*)Ks[ki];
                u64t s2 = 0ull;
#pragma unroll
                for (int i = 0; i < 16; i++) s2 = fma2(q2[i], k2[i], s2);
                float sa, sb_;
                upk2(sa, sb_, s2);
                float s = (sa + sb_) * RSQRT_DK;
                float p;
                if (s <= m) {
                    p = __expf(s - m);
                } else {
                    float c = __expf(m - s);
                    sum *= c;
                    u64t c2 = pk2(c, c);
#pragma unroll
                    for (int i = 0; i < 16; i++) acc2[i] = mul2(acc2[i], c2);
                    m = s;
                    p = 1.f;
                }
                sum += p;
                u64t p2 = pk2(p, p);
                const u64t* v2 = (const u64t*)Vs[ki];
#pragma unroll
                for (int i = 0; i < 16; i++) acc2[i] = fma2(p2, v2[i], acc2[i]);
            }
        }
    }
    if (active) {
        float inv = 1.f / sum;
        float4* op = (float4*)&g_O[(g*SS + qi)*DD + h*32];
#pragma unroll
        for (int i = 0; i < 8; i++) {
            float a0, a1, a2, a3;
            upk2(a0, a1, acc2[2*i]);
            upk2(a2, a3, acc2[2*i+1]);
            float4 v4;
            v4.x = a0*inv; v4.y = a1*inv; v4.z = a2*inv; v4.w = a3*inv;
            op[i] = v4;
        }
    }
}

// ---------------- variable attention (L=8) ----------------
__global__ void __launch_bounds__(64) k_attn_var() {
    __shared__ __align__(16) float Ks[8][256];
    __shared__ __align__(16) float Vs[8][256];

    int bs = blockIdx.x;
    int b = bs / SS;
    int s = bs - b*SS;
    int tid = threadIdx.x;

#pragma unroll
    for (int i = 0; i < 8; i++) {
        int f = tid + 64*i;
        int v = f >> 6;
        int dq = f & 63;
        int ga = ((b*VV + v)*SS + s)*DD + dq*4;
        *(float4*)&Ks[v][dq*4] = *(const float4*)&g_K[ga];
        *(float4*)&Vs[v][dq*4] = *(const float4*)&g_V[ga];
    }
    __syncthreads();

    int qv = tid & 7;
    int h  = tid >> 3;
    const float* qp = &g_Q[((b*VV + qv)*SS + s)*DD + h*32];
    float q[32];
#pragma unroll
    for (int i = 0; i < 8; i++) {
        float4 v4 = *(const float4*)&qp[i*4];
        q[i*4+0] = v4.x; q[i*4+1] = v4.y; q[i*4+2] = v4.z; q[i*4+3] = v4.w;
    }
    float sc[8];
    float mx = -1e30f;
#pragma unroll
    for (int v = 0; v < 8; v++) {
        float t = 0.f;
#pragma unroll
        for (int d = 0; d < 32; d++) t += q[d]*Ks[v][h*32 + d];
        t *= RSQRT_DK;
        sc[v] = t;
        mx = fmaxf(mx, t);
    }
    float sum = 0.f;
#pragma unroll
    for (int v = 0; v < 8; v++) { sc[v] = __expf(sc[v] - mx); sum += sc[v]; }
    float inv = 1.f / sum;

    float o[32];
#pragma unroll
    for (int d = 0; d < 32; d++) o[d] = 0.f;
#pragma unroll
    for (int v = 0; v < 8; v++)
#pragma unroll
        for (int d = 0; d < 32; d++) o[d] += sc[v]*Vs[v][h*32 + d];

    float* op = &g_O[((b*VV + qv)*SS + s)*DD + h*32];
#pragma unroll
    for (int i = 0; i < 8; i++) {
        float4 v4;
        v4.x = o[i*4+0]*inv; v4.y = o[i*4+1]*inv;
        v4.z = o[i*4+2]*inv; v4.w = o[i*4+3]*inv;
        *(float4*)&op[i*4] = v4;
    }
}

// ---------------- residual + layernorm ----------------
__global__ void __launch_bounds__(256) k_ln(const float* __restrict__ g1,
                                            const float* __restrict__ b1,
                                            const float* __restrict__ g2,
                                            const float* __restrict__ b2,
                                            int do_second) {
    int lane = threadIdx.x & 31;
    int w = threadIdx.x >> 5;
    int t = blockIdx.x*8 + w;
    float x[8];
    const float* ep = &g_E[t*DD];
    const float* pp = &g_P[t*DD];
#pragma unroll
    for (int j = 0; j < 8; j++) {
        int d = lane + 32*j;
        x[j] = ep[d] + pp[d];
    }
    float sm = 0.f, sq = 0.f;
#pragma unroll
    for (int j = 0; j < 8; j++) { sm += x[j]; sq += x[j]*x[j]; }
#pragma unroll
    for (int o = 16; o; o >>= 1) {
        sm += __shfl_xor_sync(0xffffffffu, sm, o);
        sq += __shfl_xor_sync(0xffffffffu, sq, o);
    }
    float mu = sm * (1.f/256.f);
    float var = sq * (1.f/256.f) - mu*mu;
    float r = rsqrtf(var + 1e-5f);
#pragma unroll
    for (int j = 0; j < 8; j++) {
        int d = lane + 32*j;
        x[j] = (x[j] - mu)*r*g1[d] + b1[d];
    }
    if (do_second) {
        float sm2 = 0.f, sq2 = 0.f;
#pragma unroll
        for (int j = 0; j < 8; j++) { sm2 += x[j]; sq2 += x[j]*x[j]; }
#pragma unroll
        for (int o = 16; o; o >>= 1) {
            sm2 += __shfl_xor_sync(0xffffffffu, sm2, o);
            sq2 += __shfl_xor_sync(0xffffffffu, sq2, o);
        }
        float mu2 = sm2 * (1.f/256.f);
        float var2 = sq2 * (1.f/256.f) - mu2*mu2;
        float r2 = rsqrtf(var2 + 1e-5f);
#pragma unroll
        for (int j = 0; j < 8; j++) {
            int d = lane + 32*j;
            x[j] = (x[j] - mu2)*r2*g2[d] + b2[d];
        }
    }
    float* eo = &g_E[t*DD];
#pragma unroll
    for (int j = 0; j < 8; j++) eo[lane + 32*j] = x[j];
}

// ---------------- final projection ----------------
__global__ void k_out_init(const float* __restrict__ pb, float* __restrict__ out) {
    int i = blockIdx.x*256 + threadIdx.x;
    if (i < BB*PP*VV) {
        int p = (i % (PP*VV)) >> 3;
        out[i] = pb[p];
    }
}

__global__ void __launch_bounds__(256) k_proj(const float* __restrict__ W,
                                              float* __restrict__ out) {
    __shared__ float Ws[64][96];
    __shared__ float Es[16][64];
    int k0 = blockIdx.x * 512;
    int tid = threadIdx.x;

    float acc[6];
    const float* erow[6];
    int wcol[6], oidx[6];
#pragma unroll
    for (int i = 0; i < 6; i++) {
        int qq = tid + 256*i;
        int bv = qq / 96;
        int p  = qq - bv*96;
        acc[i] = 0.f;
        erow[i] = &Es[bv][0];
        wcol[i] = p;
        oidx[i] = (bv >> 3)*(PP*VV) + p*VV + (bv & 7);
    }

    for (int kt = 0; kt < 8; kt++) {
        int kb = k0 + kt*64;
        __syncthreads();
#pragma unroll
        for (int i = 0; i < 6; i++) {
            int f = tid + 256*i;
            int kk = f / 24;
            int pq = f - kk*24;
            *(float4*)&Ws[kk][pq*4] = *(const float4*)&W[(kb + kk)*PP + pq*4];
        }
        {
            int bv = tid >> 4;
            int kq = tid & 15;
            *(float4*)&Es[bv][kq*4] = *(const float4*)&g_E[bv*SD + kb + kq*4];
        }
        __syncthreads();
        for (int kk = 0; kk < 64; kk++) {
#pragma unroll
            for (int i = 0; i < 6; i++)
                acc[i] += erow[i][kk] * Ws[kk][wcol[i]];
        }
    }
#pragma unroll
    for (int i = 0; i < 6; i++)
        atomicAdd(&out[oidx[i]], acc[i]);
}

// ---------------- launch ----------------
extern "C" void kernel_launch(void* const* d_in, const int* in_sizes, int n_in,
                              void* d_out, int out_size) {
    const float* x      = (const float*)d_in[0];
    const float* emb_w  = (const float*)d_in[1];
    const float* emb_b  = (const float*)d_in[2];
    const float* Wq     = (const float*)d_in[3];
    const float* bq     = (const float*)d_in[4];
    const float* Wk     = (const float*)d_in[5];
    const float* bk     = (const float*)d_in[6];
    const float* Wv     = (const float*)d_in[7];
    const float* bv     = (const float*)d_in[8];
    const float* Wo     = (const float*)d_in[9];
    const float* bo     = (const float*)d_in[10];
    const float* ln1_g  = (const float*)d_in[11];
    const float* ln1_b  = (const float*)d_in[12];
    const float* norm_g = (const float*)d_in[13];
    const float* norm_b = (const float*)d_in[14];
    const float* proj_w = (const float*)d_in[15];
    const float* proj_b = (const float*)d_in[16];
    float* out = (float*)d_out;

    cudaFuncSetAttribute(k_tgemm_qkv, cudaFuncAttributeMaxDynamicSharedMemorySize, SMEM_GEMM);
    cudaFuncSetAttribute(k_tgemm_wo,  cudaFuncAttributeMaxDynamicSharedMemorySize, SMEM_GEMM);

    k_prep<<<dim3(256, 4), 256>>>(Wq, Wk, Wv, Wo);
    k_embed<<<NT, 256>>>(x, emb_w, emb_b);

    for (int it = 0; it < 10; it++) {
        // phase A: attention over time axis
        k_tgemm_qkv<<<dim3(84, 3), 256, SMEM_GEMM>>>(bq, bk, bv);
        k_attn_time<<<dim3(3, 8, 16), 128>>>();
        k_tgemm_wo<<<84, 256, SMEM_GEMM>>>(bo);
        k_ln<<<NT/8, 256>>>(ln1_g, ln1_b, norm_g, norm_b, 1);
        // phase B: attention over variable axis
        k_tgemm_qkv<<<dim3(84, 3), 256, SMEM_GEMM>>>(bq, bk, bv);
        k_attn_var<<<BB*SS, 64>>>();
        k_tgemm_wo<<<84, 256, SMEM_GEMM>>>(bo);
        k_ln<<<NT/8, 256>>>(ln1_g, ln1_b, nullptr, nullptr, 0);
    }

    k_out_init<<<6, 256>>>(proj_b, out);
    k_proj<<<SD/512, 256>>>(proj_w, out);
}

// round 8
// speedup vs baseline: 1.7213x; 1.0033x over previous
#include <cuda_runtime.h>
#include <cuda_bf16.h>
#include <math.h>
#include <stdint.h>

// ---------------- problem constants ----------------
#define BB   2
#define SS   336
#define VV   8
#define DD   256
#define HH   8
#define DK   32
#define PP   96
#define NT   (BB*VV*SS)      // 5376 tokens
#define SD   (SS*DD)         // 86016
#define RSQRT_DK 0.17677669529663687f   // 1/sqrt(32)

// ---------------- scratch ----------------
__device__ float g_E[NT*DD];
__device__ float g_Q[NT*DD];
__device__ float g_K[NT*DD];
__device__ float g_V[NT*DD];
__device__ float g_O[NT*DD];
__device__ float g_P[NT*DD];
// transposed bf16 weight images W^T[n][k], hi/lo split: [w(4)][256][256]
__device__ __align__(16) __nv_bfloat16 g_WtH[4*65536];
__device__ __align__(16) __nv_bfloat16 g_WtL[4*65536];

// ---------------- helpers ----------------
__device__ __forceinline__ uint32_t smem_u32(const void* p) {
    uint32_t a;
    asm("{ .reg .u64 t; cvta.to.shared.u64 t, %1; cvt.u32.u64 %0, t; }" : "=r"(a) : "l"(p));
    return a;
}
__device__ __forceinline__ void ldsm4(uint32_t& r0, uint32_t& r1, uint32_t& r2, uint32_t& r3,
                                      uint32_t a) {
    asm volatile("ldmatrix.sync.aligned.m8n8.x4.shared.b16 {%0,%1,%2,%3}, [%4];"
        : "=r"(r0), "=r"(r1), "=r"(r2), "=r"(r3) : "r"(a));
}
__device__ __forceinline__ void mma16816(float* c, const uint32_t* a, const uint32_t* b) {
    asm volatile("mma.sync.aligned.m16n8k16.row.col.f32.bf16.bf16.f32 "
        "{%0,%1,%2,%3}, {%4,%5,%6,%7}, {%8,%9}, {%0,%1,%2,%3};"
        : "+f"(c[0]), "+f"(c[1]), "+f"(c[2]), "+f"(c[3])
        : "r"(a[0]), "r"(a[1]), "r"(a[2]), "r"(a[3]), "r"(b[0]), "r"(b[1]));
}
// packed f32x2 ops
typedef unsigned long long u64t;
__device__ __forceinline__ u64t pk2(float lo, float hi) {
    u64t r; asm("mov.b64 %0, {%1, %2};" : "=l"(r) : "f"(lo), "f"(hi)); return r;
}
__device__ __forceinline__ void upk2(float& lo, float& hi, u64t v) {
    asm("mov.b64 {%0, %1}, %2;" : "=f"(lo), "=f"(hi) : "l"(v));
}
__device__ __forceinline__ u64t fma2(u64t a, u64t b, u64t c) {
    u64t d; asm("fma.rn.f32x2 %0, %1, %2, %3;" : "=l"(d) : "l"(a), "l"(b), "l"(c)); return d;
}
__device__ __forceinline__ u64t mul2(u64t a, u64t b) {
    u64t d; asm("mul.rn.f32x2 %0, %1, %2;" : "=l"(d) : "l"(a), "l"(b)); return d;
}

// ---------------- embed ----------------
__global__ void k_embed(const float* __restrict__ x,
                        const float* __restrict__ ew,
                        const float* __restrict__ eb) {
    int idx = blockIdx.x * 256 + threadIdx.x;
    int d = idx & 255;
    int t = idx >> 8;
    int b = t / (VV*SS);
    int r = t - b*(VV*SS);
    int v = r / SS;
    int s = r - v*SS;
    g_E[idx] = x[(b*SS + s)*VV + v] * ew[d] + eb[d];
}

// ---------------- weight prep: W^T + bf16 hi/lo split ----------------
__global__ void k_prep(const float* __restrict__ Wq, const float* __restrict__ Wk,
                       const float* __restrict__ Wv, const float* __restrict__ Wo) {
    int e = blockIdx.x * 256 + threadIdx.x;   // 0..65535
    int w = blockIdx.y;
    int n = e >> 8, k = e & 255;
    const float* W = (w == 0) ? Wq : (w == 1) ? Wk : (w == 2) ? Wv : Wo;
    float a = W[k*256 + n];
    __nv_bfloat16 h = __float2bfloat16(a);
    __nv_bfloat16 l = __float2bfloat16(a - __bfloat162float(h));
    g_WtH[w*65536 + n*256 + k] = h;
    g_WtL[w*65536 + n*256 + k] = l;
}

// ---------------- mma.sync bf16x3 GEMM: C[5376,256] = A @ W + bias ----------------
// CTA tile 64x256, 8 warps (warp tile 32x64), K-chunks of 64, padded smem rows (144B).
#define GA_H 0
#define GA_L 9216
#define GB_H 18432
#define GB_L 55296
#define SMEM_GEMM 92160

__device__ __forceinline__ void tgemm_body(char* sm, const float* __restrict__ A,
                                           const __nv_bfloat16* __restrict__ WtH,
                                           const __nv_bfloat16* __restrict__ WtL,
                                           const float* __restrict__ bias,
                                           float* __restrict__ C) {
    const int tid = threadIdx.x;
    const int wid = tid >> 5, lane = tid & 31;
    const int m0 = blockIdx.x * 64;
    const int wm = (wid & 1) * 32;        // warp m offset within CTA (0/32)
    const int wn = (wid >> 1) * 64;       // warp n offset (0/64/128/192)
    uint32_t sb = smem_u32(sm);

    float acc[2][8][4];
#pragma unroll
    for (int i = 0; i < 2; i++)
#pragma unroll
        for (int j = 0; j < 8; j++)
#pragma unroll
            for (int q = 0; q < 4; q++) acc[i][j][q] = 0.f;

    // per-thread ldmatrix base addresses
    uint32_t aRow = wm + (lane & 7) + ((lane >> 3) & 1) * 8;
    uint32_t aBase = sb + GA_H + aRow*144 + ((lane >> 4) & 1)*16;
    uint32_t bRow = wn + (lane & 7) + ((lane >> 4) & 1) * 8;
    uint32_t bBase = sb + GB_H + bRow*144 + ((lane >> 3) & 1)*16;

    for (int kc = 0; kc < 4; kc++) {
        if (kc) __syncthreads();
        // stage A chunk: 64 rows x 64 k fp32 -> bf16 hi/lo (1024 float4)
        const float4* Ag = (const float4*)(A + m0*256 + kc*64);
#pragma unroll
        for (int i = 0; i < 4; i++) {
            int f = tid + 256*i;
            int r = f >> 4, q = f & 15;
            float4 v = Ag[r*64 + q];
            __nv_bfloat16 h0 = __float2bfloat16(v.x);
            __nv_bfloat16 h1 = __float2bfloat16(v.y);
            __nv_bfloat16 h2 = __float2bfloat16(v.z);
            __nv_bfloat16 h3 = __float2bfloat16(v.w);
            __nv_bfloat16 l0 = __float2bfloat16(v.x - __bfloat162float(h0));
            __nv_bfloat16 l1 = __float2bfloat16(v.y - __bfloat162float(h1));
            __nv_bfloat16 l2 = __float2bfloat16(v.z - __bfloat162float(h2));
            __nv_bfloat16 l3 = __float2bfloat16(v.w - __bfloat162float(h3));
            uint2 hp, lp;
            hp.x = (uint32_t)__bfloat16_as_ushort(h0) | ((uint32_t)__bfloat16_as_ushort(h1) << 16);
            hp.y = (uint32_t)__bfloat16_as_ushort(h2) | ((uint32_t)__bfloat16_as_ushort(h3) << 16);
            lp.x = (uint32_t)__bfloat16_as_ushort(l0) | ((uint32_t)__bfloat16_as_ushort(l1) << 16);
            lp.y = (uint32_t)__bfloat16_as_ushort(l2) | ((uint32_t)__bfloat16_as_ushort(l3) << 16);
            uint32_t off = (uint32_t)r*144 + (uint32_t)q*8;
            *(uint2*)(sm + GA_H + off) = hp;
            *(uint2*)(sm + GA_L + off) = lp;
        }
        // stage B chunk: 256 n-rows x 64 k bf16, hi+lo (2048 uint4 each)
        const uint4* BH = (const uint4*)(WtH + kc*64);
        const uint4* BL = (const uint4*)(WtL + kc*64);
#pragma unroll
        for (int i = 0; i < 8; i++) {
            int f = tid + 256*i;
            int r = f >> 3, q = f & 7;
            uint32_t off = (uint32_t)r*144 + (uint32_t)q*16;
            *(uint4*)(sm + GB_H + off) = BH[r*32 + q];
            *(uint4*)(sm + GB_L + off) = BL[r*32 + q];
        }
        __syncthreads();

#pragma unroll
        for (int ks = 0; ks < 4; ks++) {
            uint32_t aH[2][4], aL[2][4], bH[4][4], bL[4][4];
#pragma unroll
            for (int i = 0; i < 2; i++) {
                ldsm4(aH[i][0], aH[i][1], aH[i][2], aH[i][3],
                      aBase + (uint32_t)i*2304 + (uint32_t)ks*32);
                ldsm4(aL[i][0], aL[i][1], aL[i][2], aL[i][3],
                      aBase + (GA_L - GA_H) + (uint32_t)i*2304 + (uint32_t)ks*32);
            }
#pragma unroll
            for (int j = 0; j < 4; j++) {
                ldsm4(bH[j][0], bH[j][1], bH[j][2], bH[j][3],
                      bBase + (uint32_t)j*2304 + (uint32_t)ks*32);
                ldsm4(bL[j][0], bL[j][1], bL[j][2], bL[j][3],
                      bBase + (GB_L - GB_H) + (uint32_t)j*2304 + (uint32_t)ks*32);
            }
#pragma unroll
            for (int i = 0; i < 2; i++)
#pragma unroll
                for (int j = 0; j < 4; j++) {
                    mma16816(acc[i][2*j],   aH[i], &bH[j][0]);
                    mma16816(acc[i][2*j+1], aH[i], &bH[j][2]);
                    mma16816(acc[i][2*j],   aH[i], &bL[j][0]);
                    mma16816(acc[i][2*j+1], aH[i], &bL[j][2]);
                    mma16816(acc[i][2*j],   aL[i], &bH[j][0]);
                    mma16816(acc[i][2*j+1], aL[i], &bH[j][2]);
                }
        }
    }

    // epilogue
    int tr = lane >> 2, tc = (lane & 3) * 2;
    float2 bb[8];
#pragma unroll
    for (int j = 0; j < 8; j++) {
        int cl = wn + 8*j + tc;
        bb[j].x = __ldg(&bias[cl]);
        bb[j].y = __ldg(&bias[cl+1]);
    }
#pragma unroll
    for (int i = 0; i < 2; i++) {
        int r0 = m0 + wm + 16*i + tr;
#pragma unroll
        for (int j = 0; j < 8; j++) {
            int cl = wn + 8*j + tc;
            float2 o0, o1;
            o0.x = acc[i][j][0] + bb[j].x; o0.y = acc[i][j][1] + bb[j].y;
            o1.x = acc[i][j][2] + bb[j].x; o1.y = acc[i][j][3] + bb[j].y;
            *(float2*)&C[r0*256 + cl]     = o0;
            *(float2*)&C[(r0+8)*256 + cl] = o1;
        }
    }
}

__global__ void __launch_bounds__(256, 1)
k_tgemm_qkv(const float* __restrict__ bq, const float* __restrict__ bk,
            const float* __restrict__ bv) {
    extern __shared__ char sm[];
    int y = blockIdx.y;
    const __nv_bfloat16* WH = &g_WtH[y*65536];
    const __nv_bfloat16* WL = &g_WtL[y*65536];
    const float* bias = (y == 0) ? bq : (y == 1) ? bk : bv;
    float* C = (y == 0) ? g_Q : (y == 1) ? g_K : g_V;
    tgemm_body(sm, g_E, WH, WL, bias, C);
}

__global__ void __launch_bounds__(256, 1)
k_tgemm_wo(const float* __restrict__ bo) {
    extern __shared__ char sm[];
    tgemm_body(sm, g_O, &g_WtH[3*65536], &g_WtL[3*65536], bo, g_P);
}

// ---------------- time attention (f32x2 packed math) ----------------
__global__ void __launch_bounds__(128) k_attn_time() {
    __shared__ __align__(16) float Ks[112][32];
    __shared__ __align__(16) float Vs[112][32];

    int g  = blockIdx.z;
    int h  = blockIdx.y;
    int qc = blockIdx.x;
    int tid = threadIdx.x;
    int qi = qc*112 + tid;
    bool active = tid < 112;

    u64t q2[16], acc2[16];
    float m = -1e30f, sum = 0.f;
    if (active) {
        const float4* qp = (const float4*)&g_Q[(g*SS + qi)*DD + h*32];
#pragma unroll
        for (int i = 0; i < 8; i++) {
            float4 v4 = qp[i];
            q2[2*i]   = pk2(v4.x, v4.y);
            q2[2*i+1] = pk2(v4.z, v4.w);
        }
#pragma unroll
        for (int i = 0; i < 16; i++) acc2[i] = 0ull;
    }

    for (int kt = 0; kt < 3; kt++) {
        __syncthreads();
#pragma unroll
        for (int i = 0; i < 7; i++) {
            int f = tid + 128*i;
            int ki = f >> 3;
            int dq = f & 7;
            int ga = (g*SS + kt*112 + ki)*DD + h*32 + dq*4;
            *(float4*)&Ks[ki][dq*4] = *(const float4*)&g_K[ga];
            *(float4*)&Vs[ki][dq*4] = *(const float4*)&g_V[ga];
        }
        __syncthreads();
        if (active) {
            for (int ki = 0; ki < 112; ki++) {
                const u64t* k2 = (const u64t*)Ks[ki];
                u64t s2 = 0ull;
#pragma unroll
                for (int i = 0; i < 16; i++) s2 = fma2(q2[i], k2[i], s2);
                float sa, sb_;
                upk2(sa, sb_, s2);
                float s = (sa + sb_) * RSQRT_DK;
                float p;
                if (s <= m) {
                    p = __expf(s - m);
                } else {
                    float c = __expf(m - s);
                    sum *= c;
                    u64t c2 = pk2(c, c);
#pragma unroll
                    for (int i = 0; i < 16; i++) acc2[i] = mul2(acc2[i], c2);
                    m = s;
                    p = 1.f;
                }
                sum += p;
                u64t p2 = pk2(p, p);
                const u64t* v2 = (const u64t*)Vs[ki];
#pragma unroll
                for (int i = 0; i < 16; i++) acc2[i] = fma2(p2, v2[i], acc2[i]);
            }
        }
    }
    if (active) {
        float inv = 1.f / sum;
        float4* op = (float4*)&g_O[(g*SS + qi)*DD + h*32];
#pragma unroll
        for (int i = 0; i < 8; i++) {
            float a0, a1, a2, a3;
            upk2(a0, a1, acc2[2*i]);
            upk2(a2, a3, acc2[2*i+1]);
            float4 v4;
            v4.x = a0*inv; v4.y = a1*inv; v4.z = a2*inv; v4.w = a3*inv;
            op[i] = v4;
        }
    }
}

// ---------------- variable attention (L=8) ----------------
__global__ void __launch_bounds__(64) k_attn_var() {
    __shared__ __align__(16) float Ks[8][256];
    __shared__ __align__(16) float Vs[8][256];

    int bs = blockIdx.x;
    int b = bs / SS;
    int s = bs - b*SS;
    int tid = threadIdx.x;

#pragma unroll
    for (int i = 0; i < 8; i++) {
        int f = tid + 64*i;
        int v = f >> 6;
        int dq = f & 63;
        int ga = ((b*VV + v)*SS + s)*DD + dq*4;
        *(float4*)&Ks[v][dq*4] = *(const float4*)&g_K[ga];
        *(float4*)&Vs[v][dq*4] = *(const float4*)&g_V[ga];
    }
    __syncthreads();

    int qv = tid & 7;
    int h  = tid >> 3;
    const float* qp = &g_Q[((b*VV + qv)*SS + s)*DD + h*32];
    float q[32];
#pragma unroll
    for (int i = 0; i < 8; i++) {
        float4 v4 = *(const float4*)&qp[i*4];
        q[i*4+0] = v4.x; q[i*4+1] = v4.y; q[i*4+2] = v4.z; q[i*4+3] = v4.w;
    }
    float sc[8];
    float mx = -1e30f;
#pragma unroll
    for (int v = 0; v < 8; v++) {
        float t = 0.f;
#pragma unroll
        for (int d = 0; d < 32; d++) t += q[d]*Ks[v][h*32 + d];
        t *= RSQRT_DK;
        sc[v] = t;
        mx = fmaxf(mx, t);
    }
    float sum = 0.f;
#pragma unroll
    for (int v = 0; v < 8; v++) { sc[v] = __expf(sc[v] - mx); sum += sc[v]; }
    float inv = 1.f / sum;

    float o[32];
#pragma unroll
    for (int d = 0; d < 32; d++) o[d] = 0.f;
#pragma unroll
    for (int v = 0; v < 8; v++)
#pragma unroll
        for (int d = 0; d < 32; d++) o[d] += sc[v]*Vs[v][h*32 + d];

    float* op = &g_O[((b*VV + qv)*SS + s)*DD + h*32];
#pragma unroll
    for (int i = 0; i < 8; i++) {
        float4 v4;
        v4.x = o[i*4+0]*inv; v4.y = o[i*4+1]*inv;
        v4.z = o[i*4+2]*inv; v4.w = o[i*4+3]*inv;
        *(float4*)&op[i*4] = v4;
    }
}

// ---------------- residual + layernorm ----------------
__global__ void __launch_bounds__(256) k_ln(const float* __restrict__ g1,
                                            const float* __restrict__ b1,
                                            const float* __restrict__ g2,
                                            const float* __restrict__ b2,
                                            int do_second) {
    int lane = threadIdx.x & 31;
    int w = threadIdx.x >> 5;
    int t = blockIdx.x*8 + w;
    float x[8];
    const float* ep = &g_E[t*DD];
    const float* pp = &g_P[t*DD];
#pragma unroll
    for (int j = 0; j < 8; j++) {
        int d = lane + 32*j;
        x[j] = ep[d] + pp[d];
    }
    float sm = 0.f, sq = 0.f;
#pragma unroll
    for (int j = 0; j < 8; j++) { sm += x[j]; sq += x[j]*x[j]; }
#pragma unroll
    for (int o = 16; o; o >>= 1) {
        sm += __shfl_xor_sync(0xffffffffu, sm, o);
        sq += __shfl_xor_sync(0xffffffffu, sq, o);
    }
    float mu = sm * (1.f/256.f);
    float var = sq * (1.f/256.f) - mu*mu;
    float r = rsqrtf(var + 1e-5f);
#pragma unroll
    for (int j = 0; j < 8; j++) {
        int d = lane + 32*j;
        x[j] = (x[j] - mu)*r*g1[d] + b1[d];
    }
    if (do_second) {
        float sm2 = 0.f, sq2 = 0.f;
#pragma unroll
        for (int j = 0; j < 8; j++) { sm2 += x[j]; sq2 += x[j]*x[j]; }
#pragma unroll
        for (int o = 16; o; o >>= 1) {
            sm2 += __shfl_xor_sync(0xffffffffu, sm2, o);
            sq2 += __shfl_xor_sync(0xffffffffu, sq2, o);
        }
        float mu2 = sm2 * (1.f/256.f);
        float var2 = sq2 * (1.f/256.f) - mu2*mu2;
        float r2 = rsqrtf(var2 + 1e-5f);
#pragma unroll
        for (int j = 0; j < 8; j++) {
            int d = lane + 32*j;
            x[j] = (x[j] - mu2)*r2*g2[d] + b2[d];
        }
    }
    float* eo = &g_E[t*DD];
#pragma unroll
    for (int j = 0; j < 8; j++) eo[lane + 32*j] = x[j];
}

// ---------------- final projection ----------------
__global__ void k_out_init(const float* __restrict__ pb, float* __restrict__ out) {
    int i = blockIdx.x*256 + threadIdx.x;
    if (i < BB*PP*VV) {
        int p = (i % (PP*VV)) >> 3;
        out[i] = pb[p];
    }
}

__global__ void __launch_bounds__(256) k_proj(const float* __restrict__ W,
                                              float* __restrict__ out) {
    __shared__ float Ws[64][96];
    __shared__ float Es[16][64];
    int k0 = blockIdx.x * 512;
    int tid = threadIdx.x;

    float acc[6];
    const float* erow[6];
    int wcol[6], oidx[6];
#pragma unroll
    for (int i = 0; i < 6; i++) {
        int qq = tid + 256*i;
        int bv = qq / 96;
        int p  = qq - bv*96;
        acc[i] = 0.f;
        erow[i] = &Es[bv][0];
        wcol[i] = p;
        oidx[i] = (bv >> 3)*(PP*VV) + p*VV + (bv & 7);
    }

    for (int kt = 0; kt < 8; kt++) {
        int kb = k0 + kt*64;
        __syncthreads();
#pragma unroll
        for (int i = 0; i < 6; i++) {
            int f = tid + 256*i;
            int kk = f / 24;
            int pq = f - kk*24;
            *(float4*)&Ws[kk][pq*4] = *(const float4*)&W[(kb + kk)*PP + pq*4];
        }
        {
            int bv = tid >> 4;
            int kq = tid & 15;
            *(float4*)&Es[bv][kq*4] = *(const float4*)&g_E[bv*SD + kb + kq*4];
        }
        __syncthreads();
        for (int kk = 0; kk < 64; kk++) {
#pragma unroll
            for (int i = 0; i < 6; i++)
                acc[i] += erow[i][kk] * Ws[kk][wcol[i]];
        }
    }
#pragma unroll
    for (int i = 0; i < 6; i++)
        atomicAdd(&out[oidx[i]], acc[i]);
}

// ---------------- launch ----------------
extern "C" void kernel_launch(void* const* d_in, const int* in_sizes, int n_in,
                              void* d_out, int out_size) {
    const float* x      = (const float*)d_in[0];
    const float* emb_w  = (const float*)d_in[1];
    const float* emb_b  = (const float*)d_in[2];
    const float* Wq     = (const float*)d_in[3];
    const float* bq     = (const float*)d_in[4];
    const float* Wk     = (const float*)d_in[5];
    const float* bk     = (const float*)d_in[6];
    const float* Wv     = (const float*)d_in[7];
    const float* bv     = (const float*)d_in[8];
    const float* Wo     = (const float*)d_in[9];
    const float* bo     = (const float*)d_in[10];
    const float* ln1_g  = (const float*)d_in[11];
    const float* ln1_b  = (const float*)d_in[12];
    const float* norm_g = (const float*)d_in[13];
    const float* norm_b = (const float*)d_in[14];
    const float* proj_w = (const float*)d_in[15];
    const float* proj_b = (const float*)d_in[16];
    float* out = (float*)d_out;

    cudaFuncSetAttribute(k_tgemm_qkv, cudaFuncAttributeMaxDynamicSharedMemorySize, SMEM_GEMM);
    cudaFuncSetAttribute(k_tgemm_wo,  cudaFuncAttributeMaxDynamicSharedMemorySize, SMEM_GEMM);

    k_prep<<<dim3(256, 4), 256>>>(Wq, Wk, Wv, Wo);
    k_embed<<<NT, 256>>>(x, emb_w, emb_b);

    for (int it = 0; it < 10; it++) {
        // phase A: attention over time axis
        k_tgemm_qkv<<<dim3(84, 3), 256, SMEM_GEMM>>>(bq, bk, bv);
        k_attn_time<<<dim3(3, 8, 16), 128>>>();
        k_tgemm_wo<<<84, 256, SMEM_GEMM>>>(bo);
        k_ln<<<NT/8, 256>>>(ln1_g, ln1_b, norm_g, norm_b, 1);
        // phase B: attention over variable axis
        k_tgemm_qkv<<<dim3(84, 3), 256, SMEM_GEMM>>>(bq, bk, bv);
        k_attn_var<<<BB*SS, 64>>>();
        k_tgemm_wo<<<84, 256, SMEM_GEMM>>>(bo);
        k_ln<<<NT/8, 256>>>(ln1_g, ln1_b, nullptr, nullptr, 0);
    }

    k_out_init<<<6, 256>>>(proj_b, out);
    k_proj<<<SD/512, 256>>>(proj_w, out);
}

// round 9
// speedup vs baseline: 2.5370x; 1.4738x over previous
#include <cuda_runtime.h>
#include <cuda_bf16.h>
#include <math.h>
#include <stdint.h>

// ---------------- problem constants ----------------
#define BB   2
#define SS   336
#define VV   8
#define DD   256
#define HH   8
#define DK   32
#define PP   96
#define NT   (BB*VV*SS)      // 5376 tokens
#define SD   (SS*DD)         // 86016
#define RSQRT_DK 0.17677669529663687f   // 1/sqrt(32)

// ---------------- scratch ----------------
__device__ float g_E[NT*DD];
__device__ float g_Q[NT*DD];
__device__ float g_K[NT*DD];
__device__ float g_V[NT*DD];
__device__ float g_O[NT*DD];
__device__ float g_P[NT*DD];
// transposed bf16 weight images W^T[n][k], hi/lo split: [w(4)][256][256]
__device__ __align__(16) __nv_bfloat16 g_WtH[4*65536];
__device__ __align__(16) __nv_bfloat16 g_WtL[4*65536];

// ---------------- helpers ----------------
__device__ __forceinline__ uint32_t smem_u32(const void* p) {
    uint32_t a;
    asm("{ .reg .u64 t; cvta.to.shared.u64 t, %1; cvt.u32.u64 %0, t; }" : "=r"(a) : "l"(p));
    return a;
}
__device__ __forceinline__ void ldsm4(uint32_t& r0, uint32_t& r1, uint32_t& r2, uint32_t& r3,
                                      uint32_t a) {
    asm volatile("ldmatrix.sync.aligned.m8n8.x4.shared.b16 {%0,%1,%2,%3}, [%4];"
        : "=r"(r0), "=r"(r1), "=r"(r2), "=r"(r3) : "r"(a));
}
__device__ __forceinline__ void mma16816(float* c, const uint32_t* a, const uint32_t* b) {
    asm volatile("mma.sync.aligned.m16n8k16.row.col.f32.bf16.bf16.f32 "
        "{%0,%1,%2,%3}, {%4,%5,%6,%7}, {%8,%9}, {%0,%1,%2,%3};"
        : "+f"(c[0]), "+f"(c[1]), "+f"(c[2]), "+f"(c[3])
        : "r"(a[0]), "r"(a[1]), "r"(a[2]), "r"(a[3]), "r"(b[0]), "r"(b[1]));
}
__device__ __forceinline__ void cpa16(uint32_t dst, const void* src) {
    asm volatile("cp.async.cg.shared.global [%0], [%1], 16;" :: "r"(dst), "l"(src));
}
#define CPA_COMMIT() asm volatile("cp.async.commit_group;" ::: "memory")
#define CPA_WAIT0()  asm volatile("cp.async.wait_group 0;" ::: "memory")

__device__ __forceinline__ uint32_t pk_bf2(float lo, float hi) {
    __nv_bfloat162 h = __floats2bfloat162_rn(lo, hi);
    return *(uint32_t*)&h;
}
// packed f32x2 (used in var-attention)
typedef unsigned long long u64t;

// ---------------- embed ----------------
__global__ void k_embed(const float* __restrict__ x,
                        const float* __restrict__ ew,
                        const float* __restrict__ eb) {
    int idx = blockIdx.x * 256 + threadIdx.x;
    int d = idx & 255;
    int t = idx >> 8;
    int b = t / (VV*SS);
    int r = t - b*(VV*SS);
    int v = r / SS;
    int s = r - v*SS;
    g_E[idx] = x[(b*SS + s)*VV + v] * ew[d] + eb[d];
}

// ---------------- weight prep: W^T + bf16 hi/lo split ----------------
__global__ void k_prep(const float* __restrict__ Wq, const float* __restrict__ Wk,
                       const float* __restrict__ Wv, const float* __restrict__ Wo) {
    int e = blockIdx.x * 256 + threadIdx.x;   // 0..65535
    int w = blockIdx.y;
    int n = e >> 8, k = e & 255;
    const float* W = (w == 0) ? Wq : (w == 1) ? Wk : (w == 2) ? Wv : Wo;
    float a = W[k*256 + n];
    __nv_bfloat16 h = __float2bfloat16(a);
    __nv_bfloat16 l = __float2bfloat16(a - __bfloat162float(h));
    g_WtH[w*65536 + n*256 + k] = h;
    g_WtL[w*65536 + n*256 + k] = l;
}

// ---------------- pipelined mma.sync bf16x3 GEMM: C[5376,256] = A @ W + bias ----------------
// CTA tile 64x256, 8 warps (warp tile 32x64), K-chunks of 64, double-buffered + cp.async.
#define GA(buf)  ((buf)*18432)                        // A hi @+0, lo @+9216
#define GBH(buf) (36864 + (buf)*73728)
#define GBL(buf) (36864 + (buf)*73728 + 36864)
#define SMEM_GEMM 184320

__device__ __forceinline__ void tgemm_body(char* sm, const float* __restrict__ A,
                                           const __nv_bfloat16* __restrict__ WtH,
                                           const __nv_bfloat16* __restrict__ WtL,
                                           const float* __restrict__ bias,
                                           float* __restrict__ C) {
    const int tid = threadIdx.x;
    const int wid = tid >> 5, lane = tid & 31;
    const int m0 = blockIdx.x * 64;
    const int wm = (wid & 1) * 32;
    const int wn = (wid >> 1) * 64;
    uint32_t sb = smem_u32(sm);

    float acc[2][8][4];
#pragma unroll
    for (int i = 0; i < 2; i++)
#pragma unroll
        for (int j = 0; j < 8; j++)
#pragma unroll
            for (int q = 0; q < 4; q++) acc[i][j][q] = 0.f;

    uint32_t aRow = wm + (lane & 7) + ((lane >> 3) & 1) * 8;
    uint32_t aOff = aRow*144 + ((lane >> 4) & 1)*16;
    uint32_t bRow = wn + (lane & 7) + ((lane >> 4) & 1) * 8;
    uint32_t bOff = bRow*144 + ((lane >> 3) & 1)*16;

    // prologue: A chunk0 -> regs, B chunk0 -> cp.async buf0
    float4 av[4];
    {
        const float4* Ag = (const float4*)(A + m0*256);
#pragma unroll
        for (int i = 0; i < 4; i++) {
            int f = tid + 256*i;
            av[i] = Ag[(f >> 4)*64 + (f & 15)];
        }
#pragma unroll
        for (int i = 0; i < 8; i++) {
            int f = tid + 256*i;
            int r = f >> 3, q = f & 7;
            uint32_t off = (uint32_t)r*144 + (uint32_t)q*16;
            cpa16(sb + GBH(0) + off, WtH + (r << 8) + q*8);
            cpa16(sb + GBL(0) + off, WtL + (r << 8) + q*8);
        }
        CPA_COMMIT();
    }

#pragma unroll
    for (int kc = 0; kc < 4; kc++) {
        int buf = kc & 1;
        // convert A regs -> smem (hi/lo)
#pragma unroll
        for (int i = 0; i < 4; i++) {
            int f = tid + 256*i;
            int r = f >> 4, q = f & 15;
            float4 v = av[i];
            __nv_bfloat16 h0 = __float2bfloat16(v.x);
            __nv_bfloat16 h1 = __float2bfloat16(v.y);
            __nv_bfloat16 h2 = __float2bfloat16(v.z);
            __nv_bfloat16 h3 = __float2bfloat16(v.w);
            __nv_bfloat16 l0 = __float2bfloat16(v.x - __bfloat162float(h0));
            __nv_bfloat16 l1 = __float2bfloat16(v.y - __bfloat162float(h1));
            __nv_bfloat16 l2 = __float2bfloat16(v.z - __bfloat162float(h2));
            __nv_bfloat16 l3 = __float2bfloat16(v.w - __bfloat162float(h3));
            uint2 hp, lp;
            hp.x = (uint32_t)__bfloat16_as_ushort(h0) | ((uint32_t)__bfloat16_as_ushort(h1) << 16);
            hp.y = (uint32_t)__bfloat16_as_ushort(h2) | ((uint32_t)__bfloat16_as_ushort(h3) << 16);
            lp.x = (uint32_t)__bfloat16_as_ushort(l0) | ((uint32_t)__bfloat16_as_ushort(l1) << 16);
            lp.y = (uint32_t)__bfloat16_as_ushort(l2) | ((uint32_t)__bfloat16_as_ushort(l3) << 16);
            uint32_t off = (uint32_t)r*144 + (uint32_t)q*8;
            *(uint2*)(sm + GA(buf) + off)        = hp;
            *(uint2*)(sm + GA(buf) + 9216 + off) = lp;
        }
        CPA_WAIT0();
        __syncthreads();

        if (kc < 3) {
            // prefetch next A chunk, issue next B cp.async (other buffer)
            const float4* Ag = (const float4*)(A + m0*256 + (kc + 1)*64);
#pragma unroll
            for (int i = 0; i < 4; i++) {
                int f = tid + 256*i;
                av[i] = Ag[(f >> 4)*64 + (f & 15)];
            }
            int nb = buf ^ 1;
#pragma unroll
            for (int i = 0; i < 8; i++) {
                int f = tid + 256*i;
                int r = f >> 3, q = f & 7;
                uint32_t off = (uint32_t)r*144 + (uint32_t)q*16;
                cpa16(sb + GBH(nb) + off, WtH + (r << 8) + (kc + 1)*64 + q*8);
                cpa16(sb + GBL(nb) + off, WtL + (r << 8) + (kc + 1)*64 + q*8);
            }
            CPA_COMMIT();
        }

        uint32_t aB = sb + GA(buf) + aOff;
        uint32_t bB = sb + GBH(buf) + bOff;
#pragma unroll
        for (int ks = 0; ks < 4; ks++) {
            uint32_t aH[2][4], aL[2][4], bH[4][4], bL[4][4];
#pragma unroll
            for (int i = 0; i < 2; i++) {
                ldsm4(aH[i][0], aH[i][1], aH[i][2], aH[i][3],
                      aB + (uint32_t)i*2304 + (uint32_t)ks*32);
                ldsm4(aL[i][0], aL[i][1], aL[i][2], aL[i][3],
                      aB + 9216u + (uint32_t)i*2304 + (uint32_t)ks*32);
            }
#pragma unroll
            for (int j = 0; j < 4; j++) {
                ldsm4(bH[j][0], bH[j][1], bH[j][2], bH[j][3],
                      bB + (uint32_t)j*2304 + (uint32_t)ks*32);
                ldsm4(bL[j][0], bL[j][1], bL[j][2], bL[j][3],
                      bB + 36864u + (uint32_t)j*2304 + (uint32_t)ks*32);
            }
#pragma unroll
            for (int i = 0; i < 2; i++)
#pragma unroll
                for (int j = 0; j < 4; j++) {
                    mma16816(acc[i][2*j],   aH[i], &bH[j][0]);
                    mma16816(acc[i][2*j+1], aH[i], &bH[j][2]);
                    mma16816(acc[i][2*j],   aH[i], &bL[j][0]);
                    mma16816(acc[i][2*j+1], aH[i], &bL[j][2]);
                    mma16816(acc[i][2*j],   aL[i], &bH[j][0]);
                    mma16816(acc[i][2*j+1], aL[i], &bH[j][2]);
                }
        }
        __syncthreads();
    }

    // epilogue
    int tr = lane >> 2, tc = (lane & 3) * 2;
    float2 bb[8];
#pragma unroll
    for (int j = 0; j < 8; j++) {
        int cl = wn + 8*j + tc;
        bb[j].x = __ldg(&bias[cl]);
        bb[j].y = __ldg(&bias[cl+1]);
    }
#pragma unroll
    for (int i = 0; i < 2; i++) {
        int r0 = m0 + wm + 16*i + tr;
#pragma unroll
        for (int j = 0; j < 8; j++) {
            int cl = wn + 8*j + tc;
            float2 o0, o1;
            o0.x = acc[i][j][0] + bb[j].x; o0.y = acc[i][j][1] + bb[j].y;
            o1.x = acc[i][j][2] + bb[j].x; o1.y = acc[i][j][3] + bb[j].y;
            *(float2*)&C[r0*256 + cl]     = o0;
            *(float2*)&C[(r0+8)*256 + cl] = o1;
        }
    }
}

__global__ void __launch_bounds__(256, 1)
k_tgemm_qkv(const float* __restrict__ bq, const float* __restrict__ bk,
            const float* __restrict__ bv) {
    extern __shared__ char sm[];
    int y = blockIdx.y;
    const __nv_bfloat16* WH = &g_WtH[y*65536];
    const __nv_bfloat16* WL = &g_WtL[y*65536];
    const float* bias = (y == 0) ? bq : (y == 1) ? bk : bv;
    float* C = (y == 0) ? g_Q : (y == 1) ? g_K : g_V;
    tgemm_body(sm, g_E, WH, WL, bias, C);
}

__global__ void __launch_bounds__(256, 1)
k_tgemm_wo(const float* __restrict__ bo) {
    extern __shared__ char sm[];
    tgemm_body(sm, g_O, &g_WtH[3*65536], &g_WtL[3*65536], bo, g_P);
}

// ---------------- time attention: tensor-core flash, bf16x3 ----------------
// grid (3 qc, 8 h, 16 g), 256 threads = 8 warps, 16 queries per warp, key tiles of 48.
#define KT 48
__global__ void __launch_bounds__(256) k_attn_time() {
    __shared__ __nv_bfloat16 sQH[128*40], sQL[128*40];   // pitch 40 elems (80B)
    __shared__ __nv_bfloat16 sKH[48*40],  sKL[48*40];    // [key][d], pitch 80B
    __shared__ __nv_bfloat16 sVH[32*56],  sVL[32*56];    // V^T [d][key], pitch 112B

    int g  = blockIdx.z;
    int h  = blockIdx.y;
    int qb = blockIdx.x * 128;
    int tid = threadIdx.x;
    int wid = tid >> 5, lane = tid & 31;

    uint32_t uQH = smem_u32(sQH), uQL = smem_u32(sQL);
    uint32_t uKH = smem_u32(sKH), uKL = smem_u32(sKL);
    uint32_t uVH = smem_u32(sVH), uVL = smem_u32(sVL);

    // stage Q tile (128 x 32), pre-scaled by 1/sqrt(dk), hi/lo split
    {
#pragma unroll
        for (int i = 0; i < 4; i++) {
            int idx = tid + 256*i;          // 1024 float4
            int r = idx >> 3, q4 = idx & 7;
            int qi = qb + r; if (qi > 335) qi = 335;
            float4 v = *(const float4*)&g_Q[(g*SS + qi)*DD + h*32 + q4*4];
            v.x *= RSQRT_DK; v.y *= RSQRT_DK; v.z *= RSQRT_DK; v.w *= RSQRT_DK;
            __nv_bfloat16 h0 = __float2bfloat16(v.x), h1 = __float2bfloat16(v.y);
            __nv_bfloat16 h2 = __float2bfloat16(v.z), h3 = __float2bfloat16(v.w);
            __nv_bfloat16 l0 = __float2bfloat16(v.x - __bfloat162float(h0));
            __nv_bfloat16 l1 = __float2bfloat16(v.y - __bfloat162float(h1));
            __nv_bfloat16 l2 = __float2bfloat16(v.z - __bfloat162float(h2));
            __nv_bfloat16 l3 = __float2bfloat16(v.w - __bfloat162float(h3));
            uint2 hp, lp;
            hp.x = (uint32_t)__bfloat16_as_ushort(h0) | ((uint32_t)__bfloat16_as_ushort(h1) << 16);
            hp.y = (uint32_t)__bfloat16_as_ushort(h2) | ((uint32_t)__bfloat16_as_ushort(h3) << 16);
            lp.x = (uint32_t)__bfloat16_as_ushort(l0) | ((uint32_t)__bfloat16_as_ushort(l1) << 16);
            lp.y = (uint32_t)__bfloat16_as_ushort(l2) | ((uint32_t)__bfloat16_as_ushort(l3) << 16);
            *(uint2*)&sQH[r*40 + q4*4] = hp;
            *(uint2*)&sQL[r*40 + q4*4] = lp;
        }
    }
    __syncthreads();

    // load Q A-frags (m16 x k32 = 2 k16 frags, hi/lo)
    uint32_t aQoff = (uint32_t)(wid*16 + (lane & 7) + ((lane >> 3) & 1)*8)*80
                   + ((lane >> 4) & 1)*16;
    uint32_t qH[2][4], qL[2][4];
#pragma unroll
    for (int ks = 0; ks < 2; ks++) {
        ldsm4(qH[ks][0], qH[ks][1], qH[ks][2], qH[ks][3], uQH + aQoff + ks*32);
        ldsm4(qL[ks][0], qL[ks][1], qL[ks][2], qL[ks][3], uQL + aQoff + ks*32);
    }

    float o[4][4];
#pragma unroll
    for (int j = 0; j < 4; j++)
#pragma unroll
        for (int q = 0; q < 4; q++) o[j][q] = 0.f;
    float m0 = -1e30f, m1 = -1e30f, sum0 = 0.f, sum1 = 0.f;

    uint32_t kOff = (uint32_t)((lane & 7) + ((lane >> 4) & 1)*8)*80 + ((lane >> 3) & 1)*16;
    uint32_t vOff = (uint32_t)((lane & 7) + ((lane >> 4) & 1)*8)*112 + ((lane >> 3) & 1)*16;

    for (int kt = 0; kt < 7; kt++) {
        int kb0 = kt*KT;
        __syncthreads();
        // stage K (48x32) and V^T (32x48), hi/lo
#pragma unroll
        for (int i = 0; i < 3; i++) {
            int idx = tid + 256*i;            // 768 float2
            int r = idx >> 4;
            int c2 = (idx & 15)*2;
            int ga = (g*SS + kb0 + r)*DD + h*32 + c2;
            float2 kv = *(const float2*)&g_K[ga];
            float2 vv = *(const float2*)&g_V[ga];
            __nv_bfloat16 kh0 = __float2bfloat16(kv.x), kh1 = __float2bfloat16(kv.y);
            __nv_bfloat162 khp; khp.x = kh0; khp.y = kh1;
            __nv_bfloat162 klp;
            klp.x = __float2bfloat16(kv.x - __bfloat162float(kh0));
            klp.y = __float2bfloat16(kv.y - __bfloat162float(kh1));
            *(__nv_bfloat162*)&sKH[r*40 + c2] = khp;
            *(__nv_bfloat162*)&sKL[r*40 + c2] = klp;
            __nv_bfloat16 vh0 = __float2bfloat16(vv.x), vh1 = __float2bfloat16(vv.y);
            sVH[c2*56 + r]       = vh0;
            sVH[(c2+1)*56 + r]   = vh1;
            sVL[c2*56 + r]       = __float2bfloat16(vv.x - __bfloat162float(vh0));
            sVL[(c2+1)*56 + r]   = __float2bfloat16(vv.y - __bfloat162float(vh1));
        }
        __syncthreads();

        // scores S (16 x 48) = Q K^T, 3-term bf16 split
        float sc[6][4];
#pragma unroll
        for (int j = 0; j < 6; j++)
#pragma unroll
            for (int q = 0; q < 4; q++) sc[j][q] = 0.f;
#pragma unroll
        for (int ks = 0; ks < 2; ks++) {
#pragma unroll
            for (int ng = 0; ng < 3; ng++) {
                uint32_t bH[4], bL[4];
                ldsm4(bH[0], bH[1], bH[2], bH[3], uKH + kOff + ng*(16*80) + ks*32);
                ldsm4(bL[0], bL[1], bL[2], bL[3], uKL + kOff + ng*(16*80) + ks*32);
                mma16816(sc[2*ng],   qH[ks], &bH[0]);
                mma16816(sc[2*ng+1], qH[ks], &bH[2]);
                mma16816(sc[2*ng],   qH[ks], &bL[0]);
                mma16816(sc[2*ng+1], qH[ks], &bL[2]);
                mma16816(sc[2*ng],   qL[ks], &bH[0]);
                mma16816(sc[2*ng+1], qL[ks], &bH[2]);
            }
        }

        // online softmax (rows r=lane>>2 and r+8); sum reduction deferred
        float t0 = -1e30f, t1 = -1e30f;
#pragma unroll
        for (int j = 0; j < 6; j++) {
            t0 = fmaxf(t0, fmaxf(sc[j][0], sc[j][1]));
            t1 = fmaxf(t1, fmaxf(sc[j][2], sc[j][3]));
        }
        t0 = fmaxf(t0, __shfl_xor_sync(0xffffffffu, t0, 1));
        t0 = fmaxf(t0, __shfl_xor_sync(0xffffffffu, t0, 2));
        t1 = fmaxf(t1, __shfl_xor_sync(0xffffffffu, t1, 1));
        t1 = fmaxf(t1, __shfl_xor_sync(0xffffffffu, t1, 2));
        float nm0 = fmaxf(m0, t0), nm1 = fmaxf(m1, t1);
        float c0 = __expf(m0 - nm0), c1 = __expf(m1 - nm1);
        float ts0 = 0.f, ts1 = 0.f;
#pragma unroll
        for (int j = 0; j < 6; j++) {
            sc[j][0] = __expf(sc[j][0] - nm0);
            sc[j][1] = __expf(sc[j][1] - nm0);
            sc[j][2] = __expf(sc[j][2] - nm1);
            sc[j][3] = __expf(sc[j][3] - nm1);
            ts0 += sc[j][0] + sc[j][1];
            ts1 += sc[j][2] + sc[j][3];
        }
        sum0 = sum0*c0 + ts0;
        sum1 = sum1*c1 + ts1;
#pragma unroll
        for (int j = 0; j < 4; j++) {
            o[j][0] *= c0; o[j][1] *= c0; o[j][2] *= c1; o[j][3] *= c1;
        }
        m0 = nm0; m1 = nm1;

        // PV: P (16x48, hi/lo from score frags) x V (48x32), 3-term split
#pragma unroll
        for (int kb = 0; kb < 3; kb++) {
            uint32_t aP[4], aR[4];
#pragma unroll
            for (int t = 0; t < 2; t++) {
                int j = 2*kb + t;
                float x0 = sc[j][0], x1 = sc[j][1], x2 = sc[j][2], x3 = sc[j][3];
                __nv_bfloat162 h01 = __floats2bfloat162_rn(x0, x1);
                __nv_bfloat162 h23 = __floats2bfloat162_rn(x2, x3);
                aP[2*t]   = *(uint32_t*)&h01;
                aP[2*t+1] = *(uint32_t*)&h23;
                aR[2*t]   = pk_bf2(x0 - __bfloat162float(h01.x),
                                   x1 - __bfloat162float(h01.y));
                aR[2*t+1] = pk_bf2(x2 - __bfloat162float(h23.x),
                                   x3 - __bfloat162float(h23.y));
            }
#pragma unroll
            for (int ng = 0; ng < 2; ng++) {
                uint32_t vH[4], vL[4];
                ldsm4(vH[0], vH[1], vH[2], vH[3], uVH + vOff + ng*(16*112) + kb*32);
                ldsm4(vL[0], vL[1], vL[2], vL[3], uVL + vOff + ng*(16*112) + kb*32);
                mma16816(o[2*ng],   aP, &vH[0]);
                mma16816(o[2*ng+1], aP, &vH[2]);
                mma16816(o[2*ng],   aP, &vL[0]);
                mma16816(o[2*ng+1], aP, &vL[2]);
                mma16816(o[2*ng],   aR, &vH[0]);
                mma16816(o[2*ng+1], aR, &vH[2]);
            }
        }
    }

    // finalize: quad-reduce sums, normalize, store
    sum0 += __shfl_xor_sync(0xffffffffu, sum0, 1);
    sum0 += __shfl_xor_sync(0xffffffffu, sum0, 2);
    sum1 += __shfl_xor_sync(0xffffffffu, sum1, 1);
    sum1 += __shfl_xor_sync(0xffffffffu, sum1, 2);
    float inv0 = 1.f / sum0, inv1 = 1.f / sum1;
    int q0 = qb + wid*16 + (lane >> 2);
    int q1 = q0 + 8;
    int cbase = h*32 + 2*(lane & 3);
#pragma unroll
    for (int j = 0; j < 4; j++) {
        int col = cbase + 8*j;
        if (q0 < 336) {
            float2 w0; w0.x = o[j][0]*inv0; w0.y = o[j][1]*inv0;
            *(float2*)&g_O[(g*SS + q0)*DD + col] = w0;
        }
        if (q1 < 336) {
            float2 w1; w1.x = o[j][2]*inv1; w1.y = o[j][3]*inv1;
            *(float2*)&g_O[(g*SS + q1)*DD + col] = w1;
        }
    }
}

// ---------------- variable attention (L=8) ----------------
__global__ void __launch_bounds__(64) k_attn_var() {
    __shared__ __align__(16) float Ks[8][256];
    __shared__ __align__(16) float Vs[8][256];

    int bs = blockIdx.x;
    int b = bs / SS;
    int s = bs - b*SS;
    int tid = threadIdx.x;

#pragma unroll
    for (int i = 0; i < 8; i++) {
        int f = tid + 64*i;
        int v = f >> 6;
        int dq = f & 63;
        int ga = ((b*VV + v)*SS + s)*DD + dq*4;
        *(float4*)&Ks[v][dq*4] = *(const float4*)&g_K[ga];
        *(float4*)&Vs[v][dq*4] = *(const float4*)&g_V[ga];
    }
    __syncthreads();

    int qv = tid & 7;
    int h  = tid >> 3;
    const float* qp = &g_Q[((b*VV + qv)*SS + s)*DD + h*32];
    float q[32];
#pragma unroll
    for (int i = 0; i < 8; i++) {
        float4 v4 = *(const float4*)&qp[i*4];
        q[i*4+0] = v4.x; q[i*4+1] = v4.y; q[i*4+2] = v4.z; q[i*4+3] = v4.w;
    }
    float sc[8];
    float mx = -1e30f;
#pragma unroll
    for (int v = 0; v < 8; v++) {
        float t = 0.f;
#pragma unroll
        for (int d = 0; d < 32; d++) t += q[d]*Ks[v][h*32 + d];
        t *= RSQRT_DK;
        sc[v] = t;
        mx = fmaxf(mx, t);
    }
    float sum = 0.f;
#pragma unroll
    for (int v = 0; v < 8; v++) { sc[v] = __expf(sc[v] - mx); sum += sc[v]; }
    float inv = 1.f / sum;

    float o[32];
#pragma unroll
    for (int d = 0; d < 32; d++) o[d] = 0.f;
#pragma unroll
    for (int v = 0; v < 8; v++)
#pragma unroll
        for (int d = 0; d < 32; d++) o[d] += sc[v]*Vs[v][h*32 + d];

    float* op = &g_O[((b*VV + qv)*SS + s)*DD + h*32];
#pragma unroll
    for (int i = 0; i < 8; i++) {
        float4 v4;
        v4.x = o[i*4+0]*inv; v4.y = o[i*4+1]*inv;
        v4.z = o[i*4+2]*inv; v4.w = o[i*4+3]*inv;
        *(float4*)&op[i*4] = v4;
    }
}

// ---------------- residual + layernorm ----------------
__global__ void __launch_bounds__(256) k_ln(const float* __restrict__ g1,
                                            const float* __restrict__ b1,
                                            const float* __restrict__ g2,
                                            const float* __restrict__ b2,
                                            int do_second) {
    int lane = threadIdx.x & 31;
    int w = threadIdx.x >> 5;
    int t = blockIdx.x*8 + w;
    float x[8];
    const float* ep = &g_E[t*DD];
    const float* pp = &g_P[t*DD];
#pragma unroll
    for (int j = 0; j < 8; j++) {
        int d = lane + 32*j;
        x[j] = ep[d] + pp[d];
    }
    float sm = 0.f, sq = 0.f;
#pragma unroll
    for (int j = 0; j < 8; j++) { sm += x[j]; sq += x[j]*x[j]; }
#pragma unroll
    for (int o = 16; o; o >>= 1) {
        sm += __shfl_xor_sync(0xffffffffu, sm, o);
        sq += __shfl_xor_sync(0xffffffffu, sq, o);
    }
    float mu = sm * (1.f/256.f);
    float var = sq * (1.f/256.f) - mu*mu;
    float r = rsqrtf(var + 1e-5f);
#pragma unroll
    for (int j = 0; j < 8; j++) {
        int d = lane + 32*j;
        x[j] = (x[j] - mu)*r*g1[d] + b1[d];
    }
    if (do_second) {
        float sm2 = 0.f, sq2 = 0.f;
#pragma unroll
        for (int j = 0; j < 8; j++) { sm2 += x[j]; sq2 += x[j]*x[j]; }
#pragma unroll
        for (int o = 16; o; o >>= 1) {
            sm2 += __shfl_xor_sync(0xffffffffu, sm2, o);
            sq2 += __shfl_xor_sync(0xffffffffu, sq2, o);
        }
        float mu2 = sm2 * (1.f/256.f);
        float var2 = sq2 * (1.f/256.f) - mu2*mu2;
        float r2 = rsqrtf(var2 + 1e-5f);
#pragma unroll
        for (int j = 0; j < 8; j++) {
            int d = lane + 32*j;
            x[j] = (x[j] - mu2)*r2*g2[d] + b2[d];
        }
    }
    float* eo = &g_E[t*DD];
#pragma unroll
    for (int j = 0; j < 8; j++) eo[lane + 32*j] = x[j];
}

// ---------------- final projection ----------------
__global__ void k_out_init(const float* __restrict__ pb, float* __restrict__ out) {
    int i = blockIdx.x*256 + threadIdx.x;
    if (i < BB*PP*VV) {
        int p = (i % (PP*VV)) >> 3;
        out[i] = pb[p];
    }
}

__global__ void __launch_bounds__(256) k_proj(const float* __restrict__ W,
                                              float* __restrict__ out) {
    __shared__ float Ws[64][96];
    __shared__ float Es[16][64];
    int k0 = blockIdx.x * 512;
    int tid = threadIdx.x;

    float acc[6];
    const float* erow[6];
    int wcol[6], oidx[6];
#pragma unroll
    for (int i = 0; i < 6; i++) {
        int qq = tid + 256*i;
        int bv = qq / 96;
        int p  = qq - bv*96;
        acc[i] = 0.f;
        erow[i] = &Es[bv][0];
        wcol[i] = p;
        oidx[i] = (bv >> 3)*(PP*VV) + p*VV + (bv & 7);
    }

    for (int kt = 0; kt < 8; kt++) {
        int kb = k0 + kt*64;
        __syncthreads();
#pragma unroll
        for (int i = 0; i < 6; i++) {
            int f = tid + 256*i;
            int kk = f / 24;
            int pq = f - kk*24;
            *(float4*)&Ws[kk][pq*4] = *(const float4*)&W[(kb + kk)*PP + pq*4];
        }
        {
            int bv = tid >> 4;
            int kq = tid & 15;
            *(float4*)&Es[bv][kq*4] = *(const float4*)&g_E[bv*SD + kb + kq*4];
        }
        __syncthreads();
        for (int kk = 0; kk < 64; kk++) {
#pragma unroll
            for (int i = 0; i < 6; i++)
                acc[i] += erow[i][kk] * Ws[kk][wcol[i]];
        }
    }
#pragma unroll
    for (int i = 0; i < 6; i++)
        atomicAdd(&out[oidx[i]], acc[i]);
}

// ---------------- launch ----------------
extern "C" void kernel_launch(void* const* d_in, const int* in_sizes, int n_in,
                              void* d_out, int out_size) {
    const float* x      = (const float*)d_in[0];
    const float* emb_w  = (const float*)d_in[1];
    const float* emb_b  = (const float*)d_in[2];
    const float* Wq     = (const float*)d_in[3];
    const float* bq     = (const float*)d_in[4];
    const float* Wk     = (const float*)d_in[5];
    const float* bk     = (const float*)d_in[6];
    const float* Wv     = (const float*)d_in[7];
    const float* bv     = (const float*)d_in[8];
    const float* Wo     = (const float*)d_in[9];
    const float* bo     = (const float*)d_in[10];
    const float* ln1_g  = (const float*)d_in[11];
    const float* ln1_b  = (const float*)d_in[12];
    const float* norm_g = (const float*)d_in[13];
    const float* norm_b = (const float*)d_in[14];
    const float* proj_w = (const float*)d_in[15];
    const float* proj_b = (const float*)d_in[16];
    float* out = (float*)d_out;

    cudaFuncSetAttribute(k_tgemm_qkv, cudaFuncAttributeMaxDynamicSharedMemorySize, SMEM_GEMM);
    cudaFuncSetAttribute(k_tgemm_wo,  cudaFuncAttributeMaxDynamicSharedMemorySize, SMEM_GEMM);

    k_prep<<<dim3(256, 4), 256>>>(Wq, Wk, Wv, Wo);
    k_embed<<<NT, 256>>>(x, emb_w, emb_b);

    for (int it = 0; it < 10; it++) {
        // phase A: attention over time axis
        k_tgemm_qkv<<<dim3(84, 3), 256, SMEM_GEMM>>>(bq, bk, bv);
        k_attn_time<<<dim3(3, 8, 16), 256>>>();
        k_tgemm_wo<<<84, 256, SMEM_GEMM>>>(bo);
        k_ln<<<NT/8, 256>>>(ln1_g, ln1_b, norm_g, norm_b, 1);
        // phase B: attention over variable axis
        k_tgemm_qkv<<<dim3(84, 3), 256, SMEM_GEMM>>>(bq, bk, bv);
        k_attn_var<<<BB*SS, 64>>>();
        k_tgemm_wo<<<84, 256, SMEM_GEMM>>>(bo);
        k_ln<<<NT/8, 256>>>(ln1_g, ln1_b, nullptr, nullptr, 0);
    }

    k_out_init<<<6, 256>>>(proj_b, out);
    k_proj<<<SD/512, 256>>>(proj_w, out);
}